// round 15
// baseline (speedup 1.0000x reference)
#include <cuda_runtime.h>
#include <cuda_bf16.h>
#include <cstdint>

#define ULL unsigned long long

// ---------------------------------------------------------------------------
// Packed f32x2 helpers.
// ---------------------------------------------------------------------------
__device__ __forceinline__ ULL dup2(float v) {
    ULL r; asm("mov.b64 %0, {%1, %1};" : "=l"(r) : "f"(v)); return r;
}
__device__ __forceinline__ ULL pk2(float lo, float hi) {
    ULL r; asm("mov.b64 %0, {%1, %2};" : "=l"(r) : "f"(lo), "f"(hi)); return r;
}
__device__ __forceinline__ void fma2(ULL& d, ULL a, ULL b) {
    asm("fma.rn.f32x2 %0, %1, %2, %0;" : "+l"(d) : "l"(a), "l"(b));
}
__device__ __forceinline__ void add2(ULL& d, ULL a) {
    asm("add.rn.f32x2 %0, %0, %1;" : "+l"(d) : "l"(a));
}
__device__ __forceinline__ void unpk(ULL v, float& lo, float& hi) {
    asm("mov.b64 {%0, %1}, %2;" : "=f"(lo), "=f"(hi) : "l"(v));
}

__device__ __forceinline__ float sig_f(float x) {
    return __fdividef(1.0f, 1.0f + __expf(-x));
}
__device__ __forceinline__ float tanh_f(float x) {
    return __fdividef(2.0f, 1.0f + __expf(-2.0f * x)) - 1.0f;
}

__device__ __forceinline__ uint32_t smem_u32(const void* p) {
    uint32_t a;
    asm("{ .reg .u64 t; cvta.to.shared.u64 t, %1; cvt.u32.u64 %0, t; }"
        : "=r"(a) : "l"(p));
    return a;
}

// baseline-PTX tensor ops (sm_80-level; safe on compute_103)
__device__ __forceinline__ void ldsm4(uint32_t* r, uint32_t addr) {
    asm volatile("ldmatrix.sync.aligned.m8n8.x4.shared.b16 {%0,%1,%2,%3}, [%4];"
                 : "=r"(r[0]), "=r"(r[1]), "=r"(r[2]), "=r"(r[3]) : "r"(addr));
}
__device__ __forceinline__ void mma16816(float* d, const uint32_t* a,
                                         uint32_t b0, uint32_t b1) {
    asm volatile("mma.sync.aligned.m16n8k16.row.col.f32.bf16.bf16.f32 "
                 "{%0,%1,%2,%3}, {%4,%5,%6,%7}, {%8,%9}, {%0,%1,%2,%3};"
                 : "+f"(d[0]), "+f"(d[1]), "+f"(d[2]), "+f"(d[3])
                 : "r"(a[0]), "r"(a[1]), "r"(a[2]), "r"(a[3]), "r"(b0), "r"(b1));
}

// ---------------------------------------------------------------------------
// Problem constants
// ---------------------------------------------------------------------------
static constexpr int B = 1024;
static constexpr int T = 512;

// Scratch (static device arrays: allocation-free per harness rules)
__device__ float g_y0[(size_t)B * T * 128];   // layer-0 output [b][t][dir*64+k]
__device__ float g_xg[(size_t)B * T * 512];   // fused input-gates [b*T + t][512]
__device__ float g_hcat[(size_t)B * 128];     // final hidden [hT_f, hT_b]

// Activation-row stride in ULLs
static constexpr int AS = 18;

// ---------------------------------------------------------------------------
// Kernel 1: layer-0 bidirectional LSTM, 4-way warp-uniform K-split (proven).
// ---------------------------------------------------------------------------
static constexpr int RED0_ENT = 2 * 4 * 3 * 2 * 64;
static constexpr int SMEM0 = 64 * 256 * 4 + 64 * AS * 8 + RED0_ENT * 16; // 123904

__global__ void __launch_bounds__(512, 1) lstm0_kernel(
    const float* __restrict__ x,
    const float* __restrict__ WihF, const float* __restrict__ WhhF,
    const float* __restrict__ bihF, const float* __restrict__ bhhF,
    const float* __restrict__ WihB, const float* __restrict__ WhhB,
    const float* __restrict__ bihB, const float* __restrict__ bhhB)
{
    extern __shared__ float sm[];
    float*      wt  = sm;
    ULL*        h_s = (ULL*)(sm + 64 * 256);
    ulonglong2* red = (ulonglong2*)(h_s + 64 * AS);

    const int dir = blockIdx.y;
    const int b0  = blockIdx.x * 16;
    const int tid = threadIdx.x;
    const int jj  = tid & 63;
    const int pg  = (tid >> 6) & 1;
    const int kh  = tid >> 7;

    const float* Wih = dir ? WihB : WihF;
    const float* Whh = dir ? WhhB : WhhF;
    const float* bih = dir ? bihB : bihF;
    const float* bhh = dir ? bhhB : bhhF;

    for (int sidx = tid; sidx < 256 * 64; sidx += 512) {
        int gr = sidx >> 6, kk = sidx & 63;
        wt[kk * 256 + (gr & 63) * 4 + (gr >> 6)] = Whh[sidx];
    }
    ULL wA[3], wB[3];
    #pragma unroll
    for (int c = 0; c < 3; c++) {
        wA[c] = pk2(Wih[jj * 3 + c],         Wih[(64 + jj) * 3 + c]);
        wB[c] = pk2(Wih[(128 + jj) * 3 + c], Wih[(192 + jj) * 3 + c]);
    }
    const ULL biasA = pk2(bih[jj] + bhh[jj],             bih[64 + jj] + bhh[64 + jj]);
    const ULL biasB = pk2(bih[128 + jj] + bhh[128 + jj], bih[192 + jj] + bhh[192 + jj]);

    for (int idx = tid; idx < 64 * AS; idx += 512) h_s[idx] = 0ULL;

    const float* xr[2];
    float*       yr[2];
    const int dof = dir ? 64 : 0;
    #pragma unroll
    for (int i = 0; i < 2; i++) {
        int row = 8 * pg + 2 * kh + i;
        xr[i] = x + (size_t)(b0 + row) * 1536;
        yr[i] = g_y0 + (size_t)(b0 + row) * (T * 128) + dof + jj;
    }

    float cs[2] = {0.f, 0.f};
    float hh[2] = {0.f, 0.f};
    const ULL* hp = h_s + pg * 8;
    const int kb = kh * 16;
    __syncthreads();

    for (int s = 0; s < T; s++) {
        const int t = dir ? (T - 1 - s) : s;

        float xv[2][3];
        #pragma unroll
        for (int i = 0; i < 2; i++) {
            xv[i][0] = __ldg(xr[i] + t);
            xv[i][1] = __ldg(xr[i] + 512 + t);
            xv[i][2] = __ldg(xr[i] + 1024 + t);
        }

        ULL A0[8], A1[8];
        #pragma unroll
        for (int r = 0; r < 8; r++) {
            bool own = (r >> 1) == kh;
            A0[r] = own ? biasA : 0ULL;
            A1[r] = own ? biasB : 0ULL;
        }

        #pragma unroll
        for (int kk2 = 0; kk2 < 16; kk2++) {
            int kk = kb + kk2;
            ulonglong2 w2  = *(const ulonglong2*)(wt + kk * 256 + jj * 4);
            ulonglong2 hv0 = *(const ulonglong2*)(hp + kk * AS);
            ulonglong2 hv1 = *(const ulonglong2*)(hp + kk * AS + 2);
            ulonglong2 hv2 = *(const ulonglong2*)(hp + kk * AS + 4);
            ulonglong2 hv3 = *(const ulonglong2*)(hp + kk * AS + 6);
            fma2(A0[0], w2.x, hv0.x);  fma2(A1[0], w2.y, hv0.x);
            fma2(A0[1], w2.x, hv0.y);  fma2(A1[1], w2.y, hv0.y);
            fma2(A0[2], w2.x, hv1.x);  fma2(A1[2], w2.y, hv1.x);
            fma2(A0[3], w2.x, hv1.y);  fma2(A1[3], w2.y, hv1.y);
            fma2(A0[4], w2.x, hv2.x);  fma2(A1[4], w2.y, hv2.x);
            fma2(A0[5], w2.x, hv2.y);  fma2(A1[5], w2.y, hv2.y);
            fma2(A0[6], w2.x, hv3.x);  fma2(A1[6], w2.y, hv3.x);
            fma2(A0[7], w2.x, hv3.y);  fma2(A1[7], w2.y, hv3.y);
        }
        __syncthreads();

        #pragma unroll
        for (int r = 0; r < 8; r++) {
            int kr = r >> 1, i = r & 1;
            int m = kh ^ kr;
            if (m != 0)
                red[(((pg * 4 + kr) * 3 + (m - 1)) * 2 + i) * 64 + jj]
                    = make_ulonglong2(A0[r], A1[r]);
        }
        __syncthreads();

        ULL B0[2], B1[2];
        #pragma unroll
        for (int r = 0; r < 8; r++) {
            if ((r >> 1) == kh) { B0[r & 1] = A0[r]; B1[r & 1] = A1[r]; }
        }
        #pragma unroll
        for (int m = 1; m <= 3; m++) {
            #pragma unroll
            for (int i = 0; i < 2; i++) {
                ulonglong2 q = red[(((pg * 4 + kh) * 3 + (m - 1)) * 2 + i) * 64 + jj];
                add2(B0[i], q.x);
                add2(B1[i], q.y);
            }
        }

        #pragma unroll
        for (int i = 0; i < 2; i++) {
            #pragma unroll
            for (int c = 0; c < 3; c++) {
                ULL xd = dup2(xv[i][c]);
                fma2(B0[i], wA[c], xd);
                fma2(B1[i], wB[c], xd);
            }
            float ai, af, ag, ao;
            unpk(B0[i], ai, af);
            unpk(B1[i], ag, ao);
            cs[i] = sig_f(af) * cs[i] + sig_f(ai) * tanh_f(ag);
            hh[i] = sig_f(ao) * tanh_f(cs[i]);
            yr[i][(size_t)t * 128] = hh[i];
        }

        *(ulonglong2*)(h_s + jj * AS + pg * 8 + 2 * kh)
            = make_ulonglong2(dup2(hh[0]), dup2(hh[1]));
        __syncthreads();
    }
}

// ---------------------------------------------------------------------------
// Kernel 2: xg = y0 @ W^T via mma.sync bf16x3 (fp32-equivalent precision).
// grid = (4096 M-tiles of 128 rows, 4 N-tiles of 128 gates); block = 256.
// A (y0 tile) and B (W panel) staged hi/lo bf16 in padded smem (stride 136:
// 68 words ≡ 4 mod 32 -> ldmatrix conflict-free). Warp tile 32x64.
// ---------------------------------------------------------------------------
static constexpr int ASTR = 136;                    // bf16 elems per smem row
static constexpr int PLANE = 128 * ASTR * 2;        // 34816 bytes per plane
static constexpr int SMEMG = 4 * PLANE;             // 139264

__global__ void __launch_bounds__(256, 1) xg_gemm_kernel(
    const float* __restrict__ Wf, const float* __restrict__ Wb)
{
    extern __shared__ char smg[];
    __nv_bfloat16* Ah = (__nv_bfloat16*)smg;
    __nv_bfloat16* Al = Ah + 128 * ASTR;
    __nv_bfloat16* Bh = Al + 128 * ASTR;
    __nv_bfloat16* Bl = Bh + 128 * ASTR;

    const int tid  = threadIdx.x;
    const int lane = tid & 31;
    const int wid  = tid >> 5;
    const int wm   = wid >> 1;      // 0..3, M subtile of 32
    const int wn   = wid & 1;       // 0..1, N subtile of 64

    const int ny = blockIdx.y;
    const float* W = (ny < 2 ? Wf : Wb) + (size_t)(ny & 1) * (128 * 128);
    const size_t row0 = (size_t)blockIdx.x * 128;

    // stage A (y0 tile) hi/lo
    for (int idx = tid; idx < 128 * 128; idx += 256) {
        int r = idx >> 7, k = idx & 127;
        float v = g_y0[(row0 + r) * 128 + k];
        __nv_bfloat16 hi = __float2bfloat16(v);
        __nv_bfloat16 lo = __float2bfloat16(v - __bfloat162float(hi));
        Ah[r * ASTR + k] = hi;
        Al[r * ASTR + k] = lo;
    }
    // stage B (W panel, [128 gates][128 k]) hi/lo
    for (int idx = tid; idx < 128 * 128; idx += 256) {
        int r = idx >> 7, k = idx & 127;
        float v = __ldg(W + idx);
        __nv_bfloat16 hi = __float2bfloat16(v);
        __nv_bfloat16 lo = __float2bfloat16(v - __bfloat162float(hi));
        Bh[r * ASTR + k] = hi;
        Bl[r * ASTR + k] = lo;
    }
    __syncthreads();

    const uint32_t Abase = smem_u32(Ah);
    const uint32_t Bbase = Abase + 2 * PLANE;

    // ldmatrix lane address components
    const int q  = lane >> 3;
    const int lr = lane & 7;
    const uint32_t a_lane = ((wm * 32 + (q & 1) * 8 + lr) * ASTR + (q >> 1) * 8) * 2;
    const uint32_t b_lane = ((wn * 64 + (q >> 1) * 8 + lr) * ASTR + (q & 1) * 8) * 2;

    float d[2][8][4];
    #pragma unroll
    for (int mi = 0; mi < 2; mi++)
        #pragma unroll
        for (int na = 0; na < 8; na++)
            #pragma unroll
            for (int c = 0; c < 4; c++) d[mi][na][c] = 0.0f;

    // bf16x3: (Ah,Bh), (Ah,Bl), (Al,Bh)
    #pragma unroll
    for (int s = 0; s < 3; s++) {
        uint32_t Ab = Abase + (s == 2 ? PLANE : 0);
        uint32_t Bb = Bbase + (s == 1 ? PLANE : 0);
        #pragma unroll
        for (int ks = 0; ks < 8; ks++) {
            uint32_t a[2][4], bq[4][4];
            #pragma unroll
            for (int mi = 0; mi < 2; mi++)
                ldsm4(a[mi], Ab + a_lane + (mi * 16 * ASTR + ks * 16) * 2);
            #pragma unroll
            for (int nj = 0; nj < 4; nj++)
                ldsm4(bq[nj], Bb + b_lane + (nj * 16 * ASTR + ks * 16) * 2);
            #pragma unroll
            for (int mi = 0; mi < 2; mi++) {
                #pragma unroll
                for (int na = 0; na < 8; na++)
                    mma16816(d[mi][na], a[mi],
                             bq[na >> 1][(na & 1) * 2],
                             bq[na >> 1][(na & 1) * 2 + 1]);
            }
        }
    }

    // write D: row = row0 + wm*32 + mi*16 + lane/4 (+8), col = ny*128 + wn*64 + na*8 + (lane%4)*2
    const size_t colbase = (size_t)ny * 128 + wn * 64 + (lane & 3) * 2;
    #pragma unroll
    for (int mi = 0; mi < 2; mi++) {
        size_t r = row0 + wm * 32 + mi * 16 + (lane >> 2);
        #pragma unroll
        for (int na = 0; na < 8; na++) {
            size_t c = colbase + na * 8;
            *(float2*)(g_xg + r * 512 + c)       = make_float2(d[mi][na][0], d[mi][na][1]);
            *(float2*)(g_xg + (r + 8) * 512 + c) = make_float2(d[mi][na][2], d[mi][na][3]);
        }
    }
}

// ---------------------------------------------------------------------------
// Kernel 3: layer-1 recurrence only (K=64), xg streamed from global.
// Same structure as lstm0; x-GEMM replaced by prefetched xg adds.
// ---------------------------------------------------------------------------
__global__ void __launch_bounds__(512, 1) lstm1_kernel(
    const float* __restrict__ WhhF, const float* __restrict__ bihF,
    const float* __restrict__ bhhF,
    const float* __restrict__ WhhB, const float* __restrict__ bihB,
    const float* __restrict__ bhhB)
{
    extern __shared__ float sm[];
    float*      wt  = sm;
    ULL*        h_s = (ULL*)(sm + 64 * 256);
    ulonglong2* red = (ulonglong2*)(h_s + 64 * AS);

    const int dir = blockIdx.y;
    const int b0  = blockIdx.x * 16;
    const int tid = threadIdx.x;
    const int jj  = tid & 63;
    const int pg  = (tid >> 6) & 1;
    const int kh  = tid >> 7;

    const float* Whh = dir ? WhhB : WhhF;
    const float* bih = dir ? bihB : bihF;
    const float* bhh = dir ? bhhB : bhhF;

    for (int sidx = tid; sidx < 256 * 64; sidx += 512) {
        int gr = sidx >> 6, kk = sidx & 63;
        wt[kk * 256 + (gr & 63) * 4 + (gr >> 6)] = Whh[sidx];
    }
    const ULL biasA = pk2(bih[jj] + bhh[jj],             bih[64 + jj] + bhh[64 + jj]);
    const ULL biasB = pk2(bih[128 + jj] + bhh[128 + jj], bih[192 + jj] + bhh[192 + jj]);

    for (int idx = tid; idx < 64 * AS; idx += 512) h_s[idx] = 0ULL;

    const float* xgp[2];
    const int dof = dir ? 64 : 0;
    #pragma unroll
    for (int i = 0; i < 2; i++) {
        int row = 8 * pg + 2 * kh + i;
        xgp[i] = g_xg + (size_t)(b0 + row) * T * 512 + (size_t)dir * 256 + jj;
    }

    float cs[2] = {0.f, 0.f};
    float hh[2] = {0.f, 0.f};
    const ULL* hp = h_s + pg * 8;
    const int kb = kh * 16;

    // prefetch first step's xg (4 gates x 2 rows)
    float p[2][4];
    {
        int t0 = dir ? T - 1 : 0;
        #pragma unroll
        for (int i = 0; i < 2; i++) {
            #pragma unroll
            for (int g = 0; g < 4; g++)
                p[i][g] = __ldg(xgp[i] + (size_t)t0 * 512 + g * 64);
        }
    }
    __syncthreads();

    for (int s = 0; s < T; s++) {
        ULL xA[2], xB[2];
        #pragma unroll
        for (int i = 0; i < 2; i++) {
            xA[i] = pk2(p[i][0], p[i][1]);
            xB[i] = pk2(p[i][2], p[i][3]);
        }

        // prefetch next step's xg (hidden under K-loop)
        if (s + 1 < T) {
            int tn = dir ? (T - 2 - s) : (s + 1);
            #pragma unroll
            for (int i = 0; i < 2; i++) {
                #pragma unroll
                for (int g = 0; g < 4; g++)
                    p[i][g] = __ldg(xgp[i] + (size_t)tn * 512 + g * 64);
            }
        }

        ULL A0[8], A1[8];
        #pragma unroll
        for (int r = 0; r < 8; r++) {
            bool own = (r >> 1) == kh;
            A0[r] = own ? biasA : 0ULL;
            A1[r] = own ? biasB : 0ULL;
        }

        #pragma unroll
        for (int kk2 = 0; kk2 < 16; kk2++) {
            int kk = kb + kk2;
            ulonglong2 w2  = *(const ulonglong2*)(wt + kk * 256 + jj * 4);
            ulonglong2 hv0 = *(const ulonglong2*)(hp + kk * AS);
            ulonglong2 hv1 = *(const ulonglong2*)(hp + kk * AS + 2);
            ulonglong2 hv2 = *(const ulonglong2*)(hp + kk * AS + 4);
            ulonglong2 hv3 = *(const ulonglong2*)(hp + kk * AS + 6);
            fma2(A0[0], w2.x, hv0.x);  fma2(A1[0], w2.y, hv0.x);
            fma2(A0[1], w2.x, hv0.y);  fma2(A1[1], w2.y, hv0.y);
            fma2(A0[2], w2.x, hv1.x);  fma2(A1[2], w2.y, hv1.x);
            fma2(A0[3], w2.x, hv1.y);  fma2(A1[3], w2.y, hv1.y);
            fma2(A0[4], w2.x, hv2.x);  fma2(A1[4], w2.y, hv2.x);
            fma2(A0[5], w2.x, hv2.y);  fma2(A1[5], w2.y, hv2.y);
            fma2(A0[6], w2.x, hv3.x);  fma2(A1[6], w2.y, hv3.x);
            fma2(A0[7], w2.x, hv3.y);  fma2(A1[7], w2.y, hv3.y);
        }
        __syncthreads();

        #pragma unroll
        for (int r = 0; r < 8; r++) {
            int kr = r >> 1, i = r & 1;
            int m = kh ^ kr;
            if (m != 0)
                red[(((pg * 4 + kr) * 3 + (m - 1)) * 2 + i) * 64 + jj]
                    = make_ulonglong2(A0[r], A1[r]);
        }
        __syncthreads();

        ULL B0[2], B1[2];
        #pragma unroll
        for (int r = 0; r < 8; r++) {
            if ((r >> 1) == kh) { B0[r & 1] = A0[r]; B1[r & 1] = A1[r]; }
        }
        #pragma unroll
        for (int m = 1; m <= 3; m++) {
            #pragma unroll
            for (int i = 0; i < 2; i++) {
                ulonglong2 q = red[(((pg * 4 + kh) * 3 + (m - 1)) * 2 + i) * 64 + jj];
                add2(B0[i], q.x);
                add2(B1[i], q.y);
            }
        }

        #pragma unroll
        for (int i = 0; i < 2; i++) {
            add2(B0[i], xA[i]);
            add2(B1[i], xB[i]);
            float ai, af, ag, ao;
            unpk(B0[i], ai, af);
            unpk(B1[i], ag, ao);
            cs[i] = sig_f(af) * cs[i] + sig_f(ai) * tanh_f(ag);
            hh[i] = sig_f(ao) * tanh_f(cs[i]);
        }

        *(ulonglong2*)(h_s + jj * AS + pg * 8 + 2 * kh)
            = make_ulonglong2(dup2(hh[0]), dup2(hh[1]));
        __syncthreads();
    }

    #pragma unroll
    for (int i = 0; i < 2; i++) {
        int row = 8 * pg + 2 * kh + i;
        g_hcat[(size_t)(b0 + row) * 128 + dof + jj] = hh[i];
    }
}

// ---------------------------------------------------------------------------
// Kernel 4: FC head.
// ---------------------------------------------------------------------------
__global__ void __launch_bounds__(256) head_kernel(
    const float* __restrict__ fc1W, const float* __restrict__ fc1b,
    const float* __restrict__ fc2W, const float* __restrict__ fc2b,
    float* __restrict__ out)
{
    __shared__ float f1[4][64];
    const int j = threadIdx.x;
    const int r = j >> 6;
    const int o = j & 63;
    const int b = blockIdx.x * 4 + r;

    const float* h = g_hcat + (size_t)b * 128;
    const float* w = fc1W + o * 128;
    float acc = fc1b[o];
    #pragma unroll 8
    for (int kk = 0; kk < 128; kk++) acc += w[kk] * h[kk];
    f1[r][o] = fmaxf(acc, 0.0f);
    __syncthreads();

    if (o < 2) {
        float a = fc2b[o];
        const float* w2 = fc2W + o * 64;
        #pragma unroll 8
        for (int kk = 0; kk < 64; kk++) a += w2[kk] * f1[r][kk];
        out[(size_t)b * 2 + o] = a;
    }
}

// ---------------------------------------------------------------------------
// Launcher
// ---------------------------------------------------------------------------
extern "C" void kernel_launch(void* const* d_in, const int* in_sizes, int n_in,
                              void* d_out, int out_size)
{
    const float* x      = (const float*)d_in[0];
    const float* Wih0f  = (const float*)d_in[1];
    const float* Whh0f  = (const float*)d_in[2];
    const float* bih0f  = (const float*)d_in[3];
    const float* bhh0f  = (const float*)d_in[4];
    const float* Wih0b  = (const float*)d_in[5];
    const float* Whh0b  = (const float*)d_in[6];
    const float* bih0b  = (const float*)d_in[7];
    const float* bhh0b  = (const float*)d_in[8];
    const float* Wih1f  = (const float*)d_in[9];
    const float* Whh1f  = (const float*)d_in[10];
    const float* bih1f  = (const float*)d_in[11];
    const float* bhh1f  = (const float*)d_in[12];
    const float* Wih1b  = (const float*)d_in[13];
    const float* Whh1b  = (const float*)d_in[14];
    const float* bih1b  = (const float*)d_in[15];
    const float* bhh1b  = (const float*)d_in[16];
    const float* fc1W   = (const float*)d_in[17];
    const float* fc1b   = (const float*)d_in[18];
    const float* fc2W   = (const float*)d_in[19];
    const float* fc2b   = (const float*)d_in[20];
    float* out = (float*)d_out;

    cudaFuncSetAttribute(lstm0_kernel,
                         cudaFuncAttributeMaxDynamicSharedMemorySize, SMEM0);
    cudaFuncSetAttribute(xg_gemm_kernel,
                         cudaFuncAttributeMaxDynamicSharedMemorySize, SMEMG);
    cudaFuncSetAttribute(lstm1_kernel,
                         cudaFuncAttributeMaxDynamicSharedMemorySize, SMEM0);

    dim3 grid(B / 16, 2);
    lstm0_kernel<<<grid, 512, SMEM0>>>(x,
                                       Wih0f, Whh0f, bih0f, bhh0f,
                                       Wih0b, Whh0b, bih0b, bhh0b);

    dim3 ggrid(B * T / 128, 4);
    xg_gemm_kernel<<<ggrid, 256, SMEMG>>>(Wih1f, Wih1b);

    lstm1_kernel<<<grid, 512, SMEM0>>>(Whh1f, bih1f, bhh1f,
                                       Whh1b, bih1b, bhh1b);

    head_kernel<<<B / 4, 256>>>(fc1W, fc1b, fc2W, fc2b, out);
}

// round 16
// speedup vs baseline: 1.3772x; 1.3772x over previous
#include <cuda_runtime.h>
#include <cuda_bf16.h>
#include <cstdint>

#define ULL unsigned long long

// ---------------------------------------------------------------------------
// Packed f32x2 helpers.
// ---------------------------------------------------------------------------
__device__ __forceinline__ ULL dup2(float v) {
    ULL r; asm("mov.b64 %0, {%1, %1};" : "=l"(r) : "f"(v)); return r;
}
__device__ __forceinline__ ULL pk2(float lo, float hi) {
    ULL r; asm("mov.b64 %0, {%1, %2};" : "=l"(r) : "f"(lo), "f"(hi)); return r;
}
__device__ __forceinline__ void fma2(ULL& d, ULL a, ULL b) {
    asm("fma.rn.f32x2 %0, %1, %2, %0;" : "+l"(d) : "l"(a), "l"(b));
}
__device__ __forceinline__ void add2(ULL& d, ULL a) {
    asm("add.rn.f32x2 %0, %0, %1;" : "+l"(d) : "l"(a));
}
__device__ __forceinline__ void unpk(ULL v, float& lo, float& hi) {
    asm("mov.b64 {%0, %1}, %2;" : "=f"(lo), "=f"(hi) : "l"(v));
}

__device__ __forceinline__ float sig_f(float x) {
    return __fdividef(1.0f, 1.0f + __expf(-x));
}
__device__ __forceinline__ float tanh_f(float x) {
    return __fdividef(2.0f, 1.0f + __expf(-2.0f * x)) - 1.0f;
}

__device__ __forceinline__ uint32_t smem_u32(const void* p) {
    uint32_t a;
    asm("{ .reg .u64 t; cvta.to.shared.u64 t, %1; cvt.u32.u64 %0, t; }"
        : "=r"(a) : "l"(p));
    return a;
}

// baseline-PTX tensor ops (sm_80-level; safe on compute_103)
__device__ __forceinline__ void ldsm4(uint32_t* r, uint32_t addr) {
    asm volatile("ldmatrix.sync.aligned.m8n8.x4.shared.b16 {%0,%1,%2,%3}, [%4];"
                 : "=r"(r[0]), "=r"(r[1]), "=r"(r[2]), "=r"(r[3]) : "r"(addr));
}
__device__ __forceinline__ void mma16816(float* d, const uint32_t* a,
                                         uint32_t b0, uint32_t b1) {
    asm volatile("mma.sync.aligned.m16n8k16.row.col.f32.bf16.bf16.f32 "
                 "{%0,%1,%2,%3}, {%4,%5,%6,%7}, {%8,%9}, {%0,%1,%2,%3};"
                 : "+f"(d[0]), "+f"(d[1]), "+f"(d[2]), "+f"(d[3])
                 : "r"(a[0]), "r"(a[1]), "r"(a[2]), "r"(a[3]), "r"(b0), "r"(b1));
}

// ---------------------------------------------------------------------------
// Problem constants
// ---------------------------------------------------------------------------
static constexpr int B = 1024;
static constexpr int T = 512;

// Scratch (static device arrays: allocation-free per harness rules)
__device__ float g_y0[(size_t)B * T * 128];   // layer-0 output [b][t][dir*64+k]
__device__ float g_xg[(size_t)B * T * 512];   // fused input-gates [b*T + t][512]
__device__ float g_hcat[(size_t)B * 128];     // final hidden [hT_f, hT_b]
__device__ __nv_bfloat16 g_wh[512 * 128];     // Wih1 bf16 hi   [f 0-255 | b 256-511]
__device__ __nv_bfloat16 g_wl[512 * 128];     // Wih1 bf16 lo

// Activation-row stride in ULLs
static constexpr int AS = 18;

// ---------------------------------------------------------------------------
// Kernel 1: layer-0 bidirectional LSTM, 4-way warp-uniform K-split (proven).
// ---------------------------------------------------------------------------
static constexpr int RED0_ENT = 2 * 4 * 3 * 2 * 64;
static constexpr int SMEM0 = 64 * 256 * 4 + 64 * AS * 8 + RED0_ENT * 16; // 123904

__global__ void __launch_bounds__(512, 1) lstm0_kernel(
    const float* __restrict__ x,
    const float* __restrict__ WihF, const float* __restrict__ WhhF,
    const float* __restrict__ bihF, const float* __restrict__ bhhF,
    const float* __restrict__ WihB, const float* __restrict__ WhhB,
    const float* __restrict__ bihB, const float* __restrict__ bhhB)
{
    extern __shared__ float sm[];
    float*      wt  = sm;
    ULL*        h_s = (ULL*)(sm + 64 * 256);
    ulonglong2* red = (ulonglong2*)(h_s + 64 * AS);

    const int dir = blockIdx.y;
    const int b0  = blockIdx.x * 16;
    const int tid = threadIdx.x;
    const int jj  = tid & 63;
    const int pg  = (tid >> 6) & 1;
    const int kh  = tid >> 7;

    const float* Wih = dir ? WihB : WihF;
    const float* Whh = dir ? WhhB : WhhF;
    const float* bih = dir ? bihB : bihF;
    const float* bhh = dir ? bhhB : bhhF;

    for (int sidx = tid; sidx < 256 * 64; sidx += 512) {
        int gr = sidx >> 6, kk = sidx & 63;
        wt[kk * 256 + (gr & 63) * 4 + (gr >> 6)] = Whh[sidx];
    }
    ULL wA[3], wB[3];
    #pragma unroll
    for (int c = 0; c < 3; c++) {
        wA[c] = pk2(Wih[jj * 3 + c],         Wih[(64 + jj) * 3 + c]);
        wB[c] = pk2(Wih[(128 + jj) * 3 + c], Wih[(192 + jj) * 3 + c]);
    }
    const ULL biasA = pk2(bih[jj] + bhh[jj],             bih[64 + jj] + bhh[64 + jj]);
    const ULL biasB = pk2(bih[128 + jj] + bhh[128 + jj], bih[192 + jj] + bhh[192 + jj]);

    for (int idx = tid; idx < 64 * AS; idx += 512) h_s[idx] = 0ULL;

    const float* xr[2];
    float*       yr[2];
    const int dof = dir ? 64 : 0;
    #pragma unroll
    for (int i = 0; i < 2; i++) {
        int row = 8 * pg + 2 * kh + i;
        xr[i] = x + (size_t)(b0 + row) * 1536;
        yr[i] = g_y0 + (size_t)(b0 + row) * (T * 128) + dof + jj;
    }

    float cs[2] = {0.f, 0.f};
    float hh[2] = {0.f, 0.f};
    const ULL* hp = h_s + pg * 8;
    const int kb = kh * 16;
    __syncthreads();

    for (int s = 0; s < T; s++) {
        const int t = dir ? (T - 1 - s) : s;

        float xv[2][3];
        #pragma unroll
        for (int i = 0; i < 2; i++) {
            xv[i][0] = __ldg(xr[i] + t);
            xv[i][1] = __ldg(xr[i] + 512 + t);
            xv[i][2] = __ldg(xr[i] + 1024 + t);
        }

        ULL A0[8], A1[8];
        #pragma unroll
        for (int r = 0; r < 8; r++) {
            bool own = (r >> 1) == kh;
            A0[r] = own ? biasA : 0ULL;
            A1[r] = own ? biasB : 0ULL;
        }

        #pragma unroll
        for (int kk2 = 0; kk2 < 16; kk2++) {
            int kk = kb + kk2;
            ulonglong2 w2  = *(const ulonglong2*)(wt + kk * 256 + jj * 4);
            ulonglong2 hv0 = *(const ulonglong2*)(hp + kk * AS);
            ulonglong2 hv1 = *(const ulonglong2*)(hp + kk * AS + 2);
            ulonglong2 hv2 = *(const ulonglong2*)(hp + kk * AS + 4);
            ulonglong2 hv3 = *(const ulonglong2*)(hp + kk * AS + 6);
            fma2(A0[0], w2.x, hv0.x);  fma2(A1[0], w2.y, hv0.x);
            fma2(A0[1], w2.x, hv0.y);  fma2(A1[1], w2.y, hv0.y);
            fma2(A0[2], w2.x, hv1.x);  fma2(A1[2], w2.y, hv1.x);
            fma2(A0[3], w2.x, hv1.y);  fma2(A1[3], w2.y, hv1.y);
            fma2(A0[4], w2.x, hv2.x);  fma2(A1[4], w2.y, hv2.x);
            fma2(A0[5], w2.x, hv2.y);  fma2(A1[5], w2.y, hv2.y);
            fma2(A0[6], w2.x, hv3.x);  fma2(A1[6], w2.y, hv3.x);
            fma2(A0[7], w2.x, hv3.y);  fma2(A1[7], w2.y, hv3.y);
        }
        __syncthreads();

        #pragma unroll
        for (int r = 0; r < 8; r++) {
            int kr = r >> 1, i = r & 1;
            int m = kh ^ kr;
            if (m != 0)
                red[(((pg * 4 + kr) * 3 + (m - 1)) * 2 + i) * 64 + jj]
                    = make_ulonglong2(A0[r], A1[r]);
        }
        __syncthreads();

        ULL B0[2], B1[2];
        #pragma unroll
        for (int r = 0; r < 8; r++) {
            if ((r >> 1) == kh) { B0[r & 1] = A0[r]; B1[r & 1] = A1[r]; }
        }
        #pragma unroll
        for (int m = 1; m <= 3; m++) {
            #pragma unroll
            for (int i = 0; i < 2; i++) {
                ulonglong2 q = red[(((pg * 4 + kh) * 3 + (m - 1)) * 2 + i) * 64 + jj];
                add2(B0[i], q.x);
                add2(B1[i], q.y);
            }
        }

        #pragma unroll
        for (int i = 0; i < 2; i++) {
            #pragma unroll
            for (int c = 0; c < 3; c++) {
                ULL xd = dup2(xv[i][c]);
                fma2(B0[i], wA[c], xd);
                fma2(B1[i], wB[c], xd);
            }
            float ai, af, ag, ao;
            unpk(B0[i], ai, af);
            unpk(B1[i], ag, ao);
            cs[i] = sig_f(af) * cs[i] + sig_f(ai) * tanh_f(ag);
            hh[i] = sig_f(ao) * tanh_f(cs[i]);
            yr[i][(size_t)t * 128] = hh[i];
        }

        *(ulonglong2*)(h_s + jj * AS + pg * 8 + 2 * kh)
            = make_ulonglong2(dup2(hh[0]), dup2(hh[1]));
        __syncthreads();
    }
}

// ---------------------------------------------------------------------------
// Kernel 1b: W -> bf16 hi/lo pre-conversion (one-shot, trivial).
// ---------------------------------------------------------------------------
__global__ void __launch_bounds__(256) wprep_kernel(
    const float* __restrict__ Wf, const float* __restrict__ Wb)
{
    int idx = blockIdx.x * 256 + threadIdx.x;     // 0..65535
    float v = (idx < 32768) ? Wf[idx] : Wb[idx - 32768];
    __nv_bfloat16 hi = __float2bfloat16(v);
    g_wh[idx] = hi;
    g_wl[idx] = __float2bfloat16(v - __bfloat162float(hi));
}

// ---------------------------------------------------------------------------
// Kernel 2: xg = y0 @ W^T via mma.sync bf16x3.
// grid = 4096 M-tiles (128 rows each); block = 256 (8 warps: 4M x 2N of the
// 128-gate panel). A staged hi/lo ONCE; loop over 4 N-panels with uint4
// B-panel copies from pre-converted g_wh/g_wl. Padded smem stride 136
// (68 words % 32 = 4 -> ldmatrix conflict-free).
// ---------------------------------------------------------------------------
static constexpr int ASTR = 136;                    // bf16 elems per smem row
static constexpr int PLANE = 128 * ASTR * 2;        // 34816 bytes per plane
static constexpr int SMEMG = 4 * PLANE;             // 139264

__global__ void __launch_bounds__(256, 1) xg_gemm_kernel()
{
    extern __shared__ char smg[];
    __nv_bfloat16* Ah = (__nv_bfloat16*)smg;
    __nv_bfloat16* Al = Ah + 128 * ASTR;
    __nv_bfloat16* Bh = Al + 128 * ASTR;
    __nv_bfloat16* Bl = Bh + 128 * ASTR;

    const int tid  = threadIdx.x;
    const int lane = tid & 31;
    const int wid  = tid >> 5;
    const int wm   = wid >> 1;      // 0..3, M subtile of 32
    const int wn   = wid & 1;       // 0..1, N subtile of 64

    const size_t row0 = (size_t)blockIdx.x * 128;

    // stage A (y0 tile) hi/lo, vectorized: 4 floats per iter
    for (int idx = tid; idx < 128 * 32; idx += 256) {
        int r = idx >> 5, k = (idx & 31) * 4;
        float4 v = *(const float4*)(g_y0 + (row0 + r) * 128 + k);
        __nv_bfloat162 h01 = __float22bfloat162_rn(make_float2(v.x, v.y));
        __nv_bfloat162 h23 = __float22bfloat162_rn(make_float2(v.z, v.w));
        float2 hf01 = __bfloat1622float2(h01);
        float2 hf23 = __bfloat1622float2(h23);
        __nv_bfloat162 l01 = __float22bfloat162_rn(make_float2(v.x - hf01.x, v.y - hf01.y));
        __nv_bfloat162 l23 = __float22bfloat162_rn(make_float2(v.z - hf23.x, v.w - hf23.y));
        *(__nv_bfloat162*)(Ah + r * ASTR + k)     = h01;
        *(__nv_bfloat162*)(Ah + r * ASTR + k + 2) = h23;
        *(__nv_bfloat162*)(Al + r * ASTR + k)     = l01;
        *(__nv_bfloat162*)(Al + r * ASTR + k + 2) = l23;
    }

    const uint32_t Abase = smem_u32(Ah);
    const uint32_t Bbase = Abase + 2 * PLANE;

    // ldmatrix lane address components
    const int q  = lane >> 3;
    const int lr = lane & 7;
    const uint32_t a_lane = ((wm * 32 + (q & 1) * 8 + lr) * ASTR + (q >> 1) * 8) * 2;
    const uint32_t b_lane = ((wn * 64 + (q >> 1) * 8 + lr) * ASTR + (q & 1) * 8) * 2;

    for (int n = 0; n < 4; n++) {
        // stage B panel (gates n*128 .. n*128+127) via pure uint4 copies
        for (int idx = tid; idx < 128 * 16; idx += 256) {
            int r = idx >> 4, k = (idx & 15) * 8;
            *(uint4*)(Bh + r * ASTR + k) =
                *(const uint4*)(g_wh + (size_t)(n * 128 + r) * 128 + k);
            *(uint4*)(Bl + r * ASTR + k) =
                *(const uint4*)(g_wl + (size_t)(n * 128 + r) * 128 + k);
        }
        __syncthreads();   // A (first pass) + B visible

        float d[2][8][4];
        #pragma unroll
        for (int mi = 0; mi < 2; mi++)
            #pragma unroll
            for (int na = 0; na < 8; na++)
                #pragma unroll
                for (int c = 0; c < 4; c++) d[mi][na][c] = 0.0f;

        // bf16x3: (Ah,Bh), (Ah,Bl), (Al,Bh)
        #pragma unroll
        for (int s = 0; s < 3; s++) {
            uint32_t Ab = Abase + (s == 2 ? PLANE : 0);
            uint32_t Bb = Bbase + (s == 1 ? PLANE : 0);
            #pragma unroll
            for (int ks = 0; ks < 8; ks++) {
                uint32_t a[2][4], bq[4][4];
                #pragma unroll
                for (int mi = 0; mi < 2; mi++)
                    ldsm4(a[mi], Ab + a_lane + (mi * 16 * ASTR + ks * 16) * 2);
                #pragma unroll
                for (int nj = 0; nj < 4; nj++)
                    ldsm4(bq[nj], Bb + b_lane + (nj * 16 * ASTR + ks * 16) * 2);
                #pragma unroll
                for (int mi = 0; mi < 2; mi++) {
                    #pragma unroll
                    for (int na = 0; na < 8; na++)
                        mma16816(d[mi][na], a[mi],
                                 bq[na >> 1][(na & 1) * 2],
                                 bq[na >> 1][(na & 1) * 2 + 1]);
                }
            }
        }

        // write D slice
        const size_t colbase = (size_t)n * 128 + wn * 64 + (lane & 3) * 2;
        #pragma unroll
        for (int mi = 0; mi < 2; mi++) {
            size_t r = row0 + wm * 32 + mi * 16 + (lane >> 2);
            #pragma unroll
            for (int na = 0; na < 8; na++) {
                size_t c = colbase + na * 8;
                *(float2*)(g_xg + r * 512 + c)       = make_float2(d[mi][na][0], d[mi][na][1]);
                *(float2*)(g_xg + (r + 8) * 512 + c) = make_float2(d[mi][na][2], d[mi][na][3]);
            }
        }
        __syncthreads();   // B reads done before restage
    }
}

// ---------------------------------------------------------------------------
// Kernel 3: layer-1 recurrence only (K=64), xg streamed from global (proven).
// ---------------------------------------------------------------------------
__global__ void __launch_bounds__(512, 1) lstm1_kernel(
    const float* __restrict__ WhhF, const float* __restrict__ bihF,
    const float* __restrict__ bhhF,
    const float* __restrict__ WhhB, const float* __restrict__ bihB,
    const float* __restrict__ bhhB)
{
    extern __shared__ float sm[];
    float*      wt  = sm;
    ULL*        h_s = (ULL*)(sm + 64 * 256);
    ulonglong2* red = (ulonglong2*)(h_s + 64 * AS);

    const int dir = blockIdx.y;
    const int b0  = blockIdx.x * 16;
    const int tid = threadIdx.x;
    const int jj  = tid & 63;
    const int pg  = (tid >> 6) & 1;
    const int kh  = tid >> 7;

    const float* Whh = dir ? WhhB : WhhF;
    const float* bih = dir ? bihB : bihF;
    const float* bhh = dir ? bhhB : bhhF;

    for (int sidx = tid; sidx < 256 * 64; sidx += 512) {
        int gr = sidx >> 6, kk = sidx & 63;
        wt[kk * 256 + (gr & 63) * 4 + (gr >> 6)] = Whh[sidx];
    }
    const ULL biasA = pk2(bih[jj] + bhh[jj],             bih[64 + jj] + bhh[64 + jj]);
    const ULL biasB = pk2(bih[128 + jj] + bhh[128 + jj], bih[192 + jj] + bhh[192 + jj]);

    for (int idx = tid; idx < 64 * AS; idx += 512) h_s[idx] = 0ULL;

    const float* xgp[2];
    const int dof = dir ? 64 : 0;
    #pragma unroll
    for (int i = 0; i < 2; i++) {
        int row = 8 * pg + 2 * kh + i;
        xgp[i] = g_xg + (size_t)(b0 + row) * T * 512 + (size_t)dir * 256 + jj;
    }

    float cs[2] = {0.f, 0.f};
    float hh[2] = {0.f, 0.f};
    const ULL* hp = h_s + pg * 8;
    const int kb = kh * 16;

    float p[2][4];
    {
        int t0 = dir ? T - 1 : 0;
        #pragma unroll
        for (int i = 0; i < 2; i++) {
            #pragma unroll
            for (int g = 0; g < 4; g++)
                p[i][g] = __ldg(xgp[i] + (size_t)t0 * 512 + g * 64);
        }
    }
    __syncthreads();

    for (int s = 0; s < T; s++) {
        ULL xA[2], xB[2];
        #pragma unroll
        for (int i = 0; i < 2; i++) {
            xA[i] = pk2(p[i][0], p[i][1]);
            xB[i] = pk2(p[i][2], p[i][3]);
        }

        if (s + 1 < T) {
            int tn = dir ? (T - 2 - s) : (s + 1);
            #pragma unroll
            for (int i = 0; i < 2; i++) {
                #pragma unroll
                for (int g = 0; g < 4; g++)
                    p[i][g] = __ldg(xgp[i] + (size_t)tn * 512 + g * 64);
            }
        }

        ULL A0[8], A1[8];
        #pragma unroll
        for (int r = 0; r < 8; r++) {
            bool own = (r >> 1) == kh;
            A0[r] = own ? biasA : 0ULL;
            A1[r] = own ? biasB : 0ULL;
        }

        #pragma unroll
        for (int kk2 = 0; kk2 < 16; kk2++) {
            int kk = kb + kk2;
            ulonglong2 w2  = *(const ulonglong2*)(wt + kk * 256 + jj * 4);
            ulonglong2 hv0 = *(const ulonglong2*)(hp + kk * AS);
            ulonglong2 hv1 = *(const ulonglong2*)(hp + kk * AS + 2);
            ulonglong2 hv2 = *(const ulonglong2*)(hp + kk * AS + 4);
            ulonglong2 hv3 = *(const ulonglong2*)(hp + kk * AS + 6);
            fma2(A0[0], w2.x, hv0.x);  fma2(A1[0], w2.y, hv0.x);
            fma2(A0[1], w2.x, hv0.y);  fma2(A1[1], w2.y, hv0.y);
            fma2(A0[2], w2.x, hv1.x);  fma2(A1[2], w2.y, hv1.x);
            fma2(A0[3], w2.x, hv1.y);  fma2(A1[3], w2.y, hv1.y);
            fma2(A0[4], w2.x, hv2.x);  fma2(A1[4], w2.y, hv2.x);
            fma2(A0[5], w2.x, hv2.y);  fma2(A1[5], w2.y, hv2.y);
            fma2(A0[6], w2.x, hv3.x);  fma2(A1[6], w2.y, hv3.x);
            fma2(A0[7], w2.x, hv3.y);  fma2(A1[7], w2.y, hv3.y);
        }
        __syncthreads();

        #pragma unroll
        for (int r = 0; r < 8; r++) {
            int kr = r >> 1, i = r & 1;
            int m = kh ^ kr;
            if (m != 0)
                red[(((pg * 4 + kr) * 3 + (m - 1)) * 2 + i) * 64 + jj]
                    = make_ulonglong2(A0[r], A1[r]);
        }
        __syncthreads();

        ULL B0[2], B1[2];
        #pragma unroll
        for (int r = 0; r < 8; r++) {
            if ((r >> 1) == kh) { B0[r & 1] = A0[r]; B1[r & 1] = A1[r]; }
        }
        #pragma unroll
        for (int m = 1; m <= 3; m++) {
            #pragma unroll
            for (int i = 0; i < 2; i++) {
                ulonglong2 q = red[(((pg * 4 + kh) * 3 + (m - 1)) * 2 + i) * 64 + jj];
                add2(B0[i], q.x);
                add2(B1[i], q.y);
            }
        }

        #pragma unroll
        for (int i = 0; i < 2; i++) {
            add2(B0[i], xA[i]);
            add2(B1[i], xB[i]);
            float ai, af, ag, ao;
            unpk(B0[i], ai, af);
            unpk(B1[i], ag, ao);
            cs[i] = sig_f(af) * cs[i] + sig_f(ai) * tanh_f(ag);
            hh[i] = sig_f(ao) * tanh_f(cs[i]);
        }

        *(ulonglong2*)(h_s + jj * AS + pg * 8 + 2 * kh)
            = make_ulonglong2(dup2(hh[0]), dup2(hh[1]));
        __syncthreads();
    }

    #pragma unroll
    for (int i = 0; i < 2; i++) {
        int row = 8 * pg + 2 * kh + i;
        g_hcat[(size_t)(b0 + row) * 128 + dof + jj] = hh[i];
    }
}

// ---------------------------------------------------------------------------
// Kernel 4: FC head. 4 independent accumulators + float4 loads (MLP).
// ---------------------------------------------------------------------------
__global__ void __launch_bounds__(256) head_kernel(
    const float* __restrict__ fc1W, const float* __restrict__ fc1b,
    const float* __restrict__ fc2W, const float* __restrict__ fc2b,
    float* __restrict__ out)
{
    __shared__ float f1[4][64];
    const int j = threadIdx.x;
    const int r = j >> 6;
    const int o = j & 63;
    const int b = blockIdx.x * 4 + r;

    const float* h = g_hcat + (size_t)b * 128;
    const float* w = fc1W + o * 128;
    float a0 = 0.f, a1 = 0.f, a2 = 0.f, a3 = 0.f;
    #pragma unroll
    for (int kk = 0; kk < 128; kk += 4) {
        float4 wv = *(const float4*)(w + kk);
        float4 hv = *(const float4*)(h + kk);
        a0 = fmaf(wv.x, hv.x, a0);
        a1 = fmaf(wv.y, hv.y, a1);
        a2 = fmaf(wv.z, hv.z, a2);
        a3 = fmaf(wv.w, hv.w, a3);
    }
    f1[r][o] = fmaxf(fc1b[o] + (a0 + a1) + (a2 + a3), 0.0f);
    __syncthreads();

    if (o < 2) {
        const float* w2 = fc2W + o * 64;
        float c0 = 0.f, c1 = 0.f;
        #pragma unroll
        for (int kk = 0; kk < 64; kk += 2) {
            c0 = fmaf(w2[kk],     f1[r][kk],     c0);
            c1 = fmaf(w2[kk + 1], f1[r][kk + 1], c1);
        }
        out[(size_t)b * 2 + o] = fc2b[o] + c0 + c1;
    }
}

// ---------------------------------------------------------------------------
// Launcher
// ---------------------------------------------------------------------------
extern "C" void kernel_launch(void* const* d_in, const int* in_sizes, int n_in,
                              void* d_out, int out_size)
{
    const float* x      = (const float*)d_in[0];
    const float* Wih0f  = (const float*)d_in[1];
    const float* Whh0f  = (const float*)d_in[2];
    const float* bih0f  = (const float*)d_in[3];
    const float* bhh0f  = (const float*)d_in[4];
    const float* Wih0b  = (const float*)d_in[5];
    const float* Whh0b  = (const float*)d_in[6];
    const float* bih0b  = (const float*)d_in[7];
    const float* bhh0b  = (const float*)d_in[8];
    const float* Wih1f  = (const float*)d_in[9];
    const float* Whh1f  = (const float*)d_in[10];
    const float* bih1f  = (const float*)d_in[11];
    const float* bhh1f  = (const float*)d_in[12];
    const float* Wih1b  = (const float*)d_in[13];
    const float* Whh1b  = (const float*)d_in[14];
    const float* bih1b  = (const float*)d_in[15];
    const float* bhh1b  = (const float*)d_in[16];
    const float* fc1W   = (const float*)d_in[17];
    const float* fc1b   = (const float*)d_in[18];
    const float* fc2W   = (const float*)d_in[19];
    const float* fc2b   = (const float*)d_in[20];
    float* out = (float*)d_out;

    cudaFuncSetAttribute(lstm0_kernel,
                         cudaFuncAttributeMaxDynamicSharedMemorySize, SMEM0);
    cudaFuncSetAttribute(xg_gemm_kernel,
                         cudaFuncAttributeMaxDynamicSharedMemorySize, SMEMG);
    cudaFuncSetAttribute(lstm1_kernel,
                         cudaFuncAttributeMaxDynamicSharedMemorySize, SMEM0);

    wprep_kernel<<<256, 256>>>(Wih1f, Wih1b);

    dim3 grid(B / 16, 2);
    lstm0_kernel<<<grid, 512, SMEM0>>>(x,
                                       Wih0f, Whh0f, bih0f, bhh0f,
                                       Wih0b, Whh0b, bih0b, bhh0b);

    xg_gemm_kernel<<<B * T / 128, 256, SMEMG>>>();

    lstm1_kernel<<<grid, 512, SMEM0>>>(Whh1f, bih1f, bhh1f,
                                       Whh1b, bih1b, bhh1b);

    head_kernel<<<B / 4, 256>>>(fc1W, fc1b, fc2W, fc2b, out);
}

// round 17
// speedup vs baseline: 1.4079x; 1.0223x over previous
#include <cuda_runtime.h>
#include <cuda_bf16.h>
#include <cstdint>

#define ULL unsigned long long

// ---------------------------------------------------------------------------
// Packed f32x2 helpers.
// ---------------------------------------------------------------------------
__device__ __forceinline__ ULL dup2(float v) {
    ULL r; asm("mov.b64 %0, {%1, %1};" : "=l"(r) : "f"(v)); return r;
}
__device__ __forceinline__ ULL pk2(float lo, float hi) {
    ULL r; asm("mov.b64 %0, {%1, %2};" : "=l"(r) : "f"(lo), "f"(hi)); return r;
}
__device__ __forceinline__ void fma2(ULL& d, ULL a, ULL b) {
    asm("fma.rn.f32x2 %0, %1, %2, %0;" : "+l"(d) : "l"(a), "l"(b));
}
__device__ __forceinline__ void add2(ULL& d, ULL a) {
    asm("add.rn.f32x2 %0, %0, %1;" : "+l"(d) : "l"(a));
}
__device__ __forceinline__ void unpk(ULL v, float& lo, float& hi) {
    asm("mov.b64 {%0, %1}, %2;" : "=f"(lo), "=f"(hi) : "l"(v));
}

__device__ __forceinline__ float sig_f(float x) {
    return __fdividef(1.0f, 1.0f + __expf(-x));
}
__device__ __forceinline__ float tanh_f(float x) {
    return __fdividef(2.0f, 1.0f + __expf(-2.0f * x)) - 1.0f;
}

__device__ __forceinline__ uint32_t smem_u32(const void* p) {
    uint32_t a;
    asm("{ .reg .u64 t; cvta.to.shared.u64 t, %1; cvt.u32.u64 %0, t; }"
        : "=r"(a) : "l"(p));
    return a;
}

// baseline-PTX tensor ops (sm_80-level; safe on compute_103)
__device__ __forceinline__ void ldsm4(uint32_t* r, uint32_t addr) {
    asm volatile("ldmatrix.sync.aligned.m8n8.x4.shared.b16 {%0,%1,%2,%3}, [%4];"
                 : "=r"(r[0]), "=r"(r[1]), "=r"(r[2]), "=r"(r[3]) : "r"(addr));
}
__device__ __forceinline__ void mma16816(float* d, const uint32_t* a,
                                         uint32_t b0, uint32_t b1) {
    asm volatile("mma.sync.aligned.m16n8k16.row.col.f32.bf16.bf16.f32 "
                 "{%0,%1,%2,%3}, {%4,%5,%6,%7}, {%8,%9}, {%0,%1,%2,%3};"
                 : "+f"(d[0]), "+f"(d[1]), "+f"(d[2]), "+f"(d[3])
                 : "r"(a[0]), "r"(a[1]), "r"(a[2]), "r"(a[3]), "r"(b0), "r"(b1));
}

// ---------------------------------------------------------------------------
// Problem constants
// ---------------------------------------------------------------------------
static constexpr int B = 1024;
static constexpr int T = 512;

// Scratch (static device arrays: allocation-free per harness rules)
__device__ float g_y0[(size_t)B * T * 128];   // layer-0 output [b][t][dir*64+k]
__device__ float g_xg[(size_t)B * T * 512];   // fused input-gates [b*T + t][512]
__device__ float g_hcat[(size_t)B * 128];     // final hidden [hT_f, hT_b]
__device__ __nv_bfloat16 g_wh[512 * 128];     // Wih1 bf16 hi   [f 0-255 | b 256-511]
__device__ __nv_bfloat16 g_wl[512 * 128];     // Wih1 bf16 lo

// h_s row stride in ULLs (8 rows + 2 pad; 16B-aligned slots)
static constexpr int AS2 = 10;

// ---------------------------------------------------------------------------
// LSTM CTA shape: 8 batch rows, 256 threads (jj = tid&63, kh = tid>>6,
// kh warp-uniform). grid = (B/8, 2 dirs) = 256 CTAs -> 2 CTAs/SM: two
// independent barrier domains per SM hide barrier convoy + epilogue tail.
// ---------------------------------------------------------------------------
static constexpr int RED_ENT = 4 * 3 * 2 * 64;                  // ulonglong2
static constexpr int SMEML = 64 * 256 * 4 + 64 * AS2 * 8 + RED_ENT * 16; // 95232

// ---------------------------------------------------------------------------
// Kernel 1: layer-0 bidirectional LSTM.
// ---------------------------------------------------------------------------
__global__ void __launch_bounds__(256, 2) lstm0_kernel(
    const float* __restrict__ x,
    const float* __restrict__ WihF, const float* __restrict__ WhhF,
    const float* __restrict__ bihF, const float* __restrict__ bhhF,
    const float* __restrict__ WihB, const float* __restrict__ WhhB,
    const float* __restrict__ bihB, const float* __restrict__ bhhB)
{
    extern __shared__ float sm[];
    float*      wt  = sm;                          // [64][256]
    ULL*        h_s = (ULL*)(sm + 64 * 256);       // [64][AS2]
    ulonglong2* red = (ulonglong2*)(h_s + 64 * AS2);

    const int dir = blockIdx.y;
    const int b0  = blockIdx.x * 8;
    const int tid = threadIdx.x;
    const int jj  = tid & 63;
    const int kh  = tid >> 6;            // warp-uniform K quarter

    const float* Wih = dir ? WihB : WihF;
    const float* Whh = dir ? WhhB : WhhF;
    const float* bih = dir ? bihB : bihF;
    const float* bhh = dir ? bhhB : bhhF;

    // stage Whh transposed: wt[kk][j*4+g]
    for (int sidx = tid; sidx < 256 * 64; sidx += 256) {
        int gr = sidx >> 6, kk = sidx & 63;
        wt[kk * 256 + (gr & 63) * 4 + (gr >> 6)] = Whh[sidx];
    }
    ULL wA[3], wB[3];
    #pragma unroll
    for (int c = 0; c < 3; c++) {
        wA[c] = pk2(Wih[jj * 3 + c],         Wih[(64 + jj) * 3 + c]);
        wB[c] = pk2(Wih[(128 + jj) * 3 + c], Wih[(192 + jj) * 3 + c]);
    }
    const ULL biasA = pk2(bih[jj] + bhh[jj],             bih[64 + jj] + bhh[64 + jj]);
    const ULL biasB = pk2(bih[128 + jj] + bhh[128 + jj], bih[192 + jj] + bhh[192 + jj]);

    for (int idx = tid; idx < 64 * AS2; idx += 256) h_s[idx] = 0ULL;

    // finishing rows: local r = 2kh, 2kh+1
    const float* xr[2];
    float*       yr[2];
    const int dof = dir ? 64 : 0;
    #pragma unroll
    for (int i = 0; i < 2; i++) {
        int row = 2 * kh + i;
        xr[i] = x + (size_t)(b0 + row) * 1536;
        yr[i] = g_y0 + (size_t)(b0 + row) * (T * 128) + dof + jj;
    }

    float cs[2] = {0.f, 0.f};
    float hh[2] = {0.f, 0.f};
    const int kb = kh * 16;
    __syncthreads();

    for (int s = 0; s < T; s++) {
        const int t = dir ? (T - 1 - s) : s;

        float xv[2][3];
        #pragma unroll
        for (int i = 0; i < 2; i++) {
            xv[i][0] = __ldg(xr[i] + t);
            xv[i][1] = __ldg(xr[i] + 512 + t);
            xv[i][2] = __ldg(xr[i] + 1024 + t);
        }

        ULL A0[8], A1[8];
        #pragma unroll
        for (int r = 0; r < 8; r++) {
            bool own = (r >> 1) == kh;
            A0[r] = own ? biasA : 0ULL;
            A1[r] = own ? biasB : 0ULL;
        }

        #pragma unroll
        for (int kk2 = 0; kk2 < 16; kk2++) {
            int kk = kb + kk2;
            ulonglong2 w2  = *(const ulonglong2*)(wt + kk * 256 + jj * 4);
            ulonglong2 hv0 = *(const ulonglong2*)(h_s + kk * AS2);
            ulonglong2 hv1 = *(const ulonglong2*)(h_s + kk * AS2 + 2);
            ulonglong2 hv2 = *(const ulonglong2*)(h_s + kk * AS2 + 4);
            ulonglong2 hv3 = *(const ulonglong2*)(h_s + kk * AS2 + 6);
            fma2(A0[0], w2.x, hv0.x);  fma2(A1[0], w2.y, hv0.x);
            fma2(A0[1], w2.x, hv0.y);  fma2(A1[1], w2.y, hv0.y);
            fma2(A0[2], w2.x, hv1.x);  fma2(A1[2], w2.y, hv1.x);
            fma2(A0[3], w2.x, hv1.y);  fma2(A1[3], w2.y, hv1.y);
            fma2(A0[4], w2.x, hv2.x);  fma2(A1[4], w2.y, hv2.x);
            fma2(A0[5], w2.x, hv2.y);  fma2(A1[5], w2.y, hv2.y);
            fma2(A0[6], w2.x, hv3.x);  fma2(A1[6], w2.y, hv3.x);
            fma2(A0[7], w2.x, hv3.y);  fma2(A1[7], w2.y, hv3.y);
        }
        __syncthreads();   // B: all h_s reads done

        // one-shot reduction write for non-owned rows
        #pragma unroll
        for (int r = 0; r < 8; r++) {
            int kr = r >> 1, i = r & 1;
            int m = kh ^ kr;
            if (m != 0)
                red[((kr * 3 + (m - 1)) * 2 + i) * 64 + jj]
                    = make_ulonglong2(A0[r], A1[r]);
        }
        __syncthreads();   // C: partials visible

        ULL B0[2], B1[2];
        #pragma unroll
        for (int r = 0; r < 8; r++) {
            if ((r >> 1) == kh) { B0[r & 1] = A0[r]; B1[r & 1] = A1[r]; }
        }
        #pragma unroll
        for (int m = 1; m <= 3; m++) {
            #pragma unroll
            for (int i = 0; i < 2; i++) {
                ulonglong2 q = red[((kh * 3 + (m - 1)) * 2 + i) * 64 + jj];
                add2(B0[i], q.x);
                add2(B1[i], q.y);
            }
        }

        #pragma unroll
        for (int i = 0; i < 2; i++) {
            #pragma unroll
            for (int c = 0; c < 3; c++) {
                ULL xd = dup2(xv[i][c]);
                fma2(B0[i], wA[c], xd);
                fma2(B1[i], wB[c], xd);
            }
            float ai, af, ag, ao;
            unpk(B0[i], ai, af);
            unpk(B1[i], ag, ao);
            cs[i] = sig_f(af) * cs[i] + sig_f(ai) * tanh_f(ag);
            hh[i] = sig_f(ao) * tanh_f(cs[i]);
            yr[i][(size_t)t * 128] = hh[i];
        }

        *(ulonglong2*)(h_s + jj * AS2 + 2 * kh)
            = make_ulonglong2(dup2(hh[0]), dup2(hh[1]));
        __syncthreads();   // D: h(t+1) visible
    }
}

// ---------------------------------------------------------------------------
// Kernel 1b: W -> bf16 hi/lo pre-conversion (one-shot, trivial).
// ---------------------------------------------------------------------------
__global__ void __launch_bounds__(256) wprep_kernel(
    const float* __restrict__ Wf, const float* __restrict__ Wb)
{
    int idx = blockIdx.x * 256 + threadIdx.x;     // 0..65535
    float v = (idx < 32768) ? Wf[idx] : Wb[idx - 32768];
    __nv_bfloat16 hi = __float2bfloat16(v);
    g_wh[idx] = hi;
    g_wl[idx] = __float2bfloat16(v - __bfloat162float(hi));
}

// ---------------------------------------------------------------------------
// Kernel 2: xg = y0 @ W^T via mma.sync bf16x3 (proven R15).
// ---------------------------------------------------------------------------
static constexpr int ASTR = 136;                    // bf16 elems per smem row
static constexpr int PLANE = 128 * ASTR * 2;        // 34816 bytes per plane
static constexpr int SMEMG = 4 * PLANE;             // 139264

__global__ void __launch_bounds__(256, 1) xg_gemm_kernel()
{
    extern __shared__ char smg[];
    __nv_bfloat16* Ah = (__nv_bfloat16*)smg;
    __nv_bfloat16* Al = Ah + 128 * ASTR;
    __nv_bfloat16* Bh = Al + 128 * ASTR;
    __nv_bfloat16* Bl = Bh + 128 * ASTR;

    const int tid  = threadIdx.x;
    const int lane = tid & 31;
    const int wid  = tid >> 5;
    const int wm   = wid >> 1;
    const int wn   = wid & 1;

    const size_t row0 = (size_t)blockIdx.x * 128;

    for (int idx = tid; idx < 128 * 32; idx += 256) {
        int r = idx >> 5, k = (idx & 31) * 4;
        float4 v = *(const float4*)(g_y0 + (row0 + r) * 128 + k);
        __nv_bfloat162 h01 = __float22bfloat162_rn(make_float2(v.x, v.y));
        __nv_bfloat162 h23 = __float22bfloat162_rn(make_float2(v.z, v.w));
        float2 hf01 = __bfloat1622float2(h01);
        float2 hf23 = __bfloat1622float2(h23);
        __nv_bfloat162 l01 = __float22bfloat162_rn(make_float2(v.x - hf01.x, v.y - hf01.y));
        __nv_bfloat162 l23 = __float22bfloat162_rn(make_float2(v.z - hf23.x, v.w - hf23.y));
        *(__nv_bfloat162*)(Ah + r * ASTR + k)     = h01;
        *(__nv_bfloat162*)(Ah + r * ASTR + k + 2) = h23;
        *(__nv_bfloat162*)(Al + r * ASTR + k)     = l01;
        *(__nv_bfloat162*)(Al + r * ASTR + k + 2) = l23;
    }

    const uint32_t Abase = smem_u32(Ah);
    const uint32_t Bbase = Abase + 2 * PLANE;

    const int q  = lane >> 3;
    const int lr = lane & 7;
    const uint32_t a_lane = ((wm * 32 + (q & 1) * 8 + lr) * ASTR + (q >> 1) * 8) * 2;
    const uint32_t b_lane = ((wn * 64 + (q >> 1) * 8 + lr) * ASTR + (q & 1) * 8) * 2;

    for (int n = 0; n < 4; n++) {
        for (int idx = tid; idx < 128 * 16; idx += 256) {
            int r = idx >> 4, k = (idx & 15) * 8;
            *(uint4*)(Bh + r * ASTR + k) =
                *(const uint4*)(g_wh + (size_t)(n * 128 + r) * 128 + k);
            *(uint4*)(Bl + r * ASTR + k) =
                *(const uint4*)(g_wl + (size_t)(n * 128 + r) * 128 + k);
        }
        __syncthreads();

        float d[2][8][4];
        #pragma unroll
        for (int mi = 0; mi < 2; mi++)
            #pragma unroll
            for (int na = 0; na < 8; na++)
                #pragma unroll
                for (int c = 0; c < 4; c++) d[mi][na][c] = 0.0f;

        #pragma unroll
        for (int s = 0; s < 3; s++) {
            uint32_t Ab = Abase + (s == 2 ? PLANE : 0);
            uint32_t Bb = Bbase + (s == 1 ? PLANE : 0);
            #pragma unroll
            for (int ks = 0; ks < 8; ks++) {
                uint32_t a[2][4], bq[4][4];
                #pragma unroll
                for (int mi = 0; mi < 2; mi++)
                    ldsm4(a[mi], Ab + a_lane + (mi * 16 * ASTR + ks * 16) * 2);
                #pragma unroll
                for (int nj = 0; nj < 4; nj++)
                    ldsm4(bq[nj], Bb + b_lane + (nj * 16 * ASTR + ks * 16) * 2);
                #pragma unroll
                for (int mi = 0; mi < 2; mi++) {
                    #pragma unroll
                    for (int na = 0; na < 8; na++)
                        mma16816(d[mi][na], a[mi],
                                 bq[na >> 1][(na & 1) * 2],
                                 bq[na >> 1][(na & 1) * 2 + 1]);
                }
            }
        }

        const size_t colbase = (size_t)n * 128 + wn * 64 + (lane & 3) * 2;
        #pragma unroll
        for (int mi = 0; mi < 2; mi++) {
            size_t r = row0 + wm * 32 + mi * 16 + (lane >> 2);
            #pragma unroll
            for (int na = 0; na < 8; na++) {
                size_t c = colbase + na * 8;
                *(float2*)(g_xg + r * 512 + c)       = make_float2(d[mi][na][0], d[mi][na][1]);
                *(float2*)(g_xg + (r + 8) * 512 + c) = make_float2(d[mi][na][2], d[mi][na][3]);
            }
        }
        __syncthreads();
    }
}

// ---------------------------------------------------------------------------
// Kernel 3: layer-1 recurrence (K=64), xg streamed; 8 rows/CTA, 2 CTAs/SM.
// ---------------------------------------------------------------------------
__global__ void __launch_bounds__(256, 2) lstm1_kernel(
    const float* __restrict__ WhhF, const float* __restrict__ bihF,
    const float* __restrict__ bhhF,
    const float* __restrict__ WhhB, const float* __restrict__ bihB,
    const float* __restrict__ bhhB)
{
    extern __shared__ float sm[];
    float*      wt  = sm;
    ULL*        h_s = (ULL*)(sm + 64 * 256);
    ulonglong2* red = (ulonglong2*)(h_s + 64 * AS2);

    const int dir = blockIdx.y;
    const int b0  = blockIdx.x * 8;
    const int tid = threadIdx.x;
    const int jj  = tid & 63;
    const int kh  = tid >> 6;

    const float* Whh = dir ? WhhB : WhhF;
    const float* bih = dir ? bihB : bihF;
    const float* bhh = dir ? bhhB : bhhF;

    for (int sidx = tid; sidx < 256 * 64; sidx += 256) {
        int gr = sidx >> 6, kk = sidx & 63;
        wt[kk * 256 + (gr & 63) * 4 + (gr >> 6)] = Whh[sidx];
    }
    const ULL biasA = pk2(bih[jj] + bhh[jj],             bih[64 + jj] + bhh[64 + jj]);
    const ULL biasB = pk2(bih[128 + jj] + bhh[128 + jj], bih[192 + jj] + bhh[192 + jj]);

    for (int idx = tid; idx < 64 * AS2; idx += 256) h_s[idx] = 0ULL;

    const float* xgp[2];
    const int dof = dir ? 64 : 0;
    #pragma unroll
    for (int i = 0; i < 2; i++) {
        int row = 2 * kh + i;
        xgp[i] = g_xg + (size_t)(b0 + row) * T * 512 + (size_t)dir * 256 + jj;
    }

    float cs[2] = {0.f, 0.f};
    float hh[2] = {0.f, 0.f};
    const int kb = kh * 16;

    float p[2][4];
    {
        int t0 = dir ? T - 1 : 0;
        #pragma unroll
        for (int i = 0; i < 2; i++) {
            #pragma unroll
            for (int g = 0; g < 4; g++)
                p[i][g] = __ldg(xgp[i] + (size_t)t0 * 512 + g * 64);
        }
    }
    __syncthreads();

    for (int s = 0; s < T; s++) {
        ULL xA[2], xB[2];
        #pragma unroll
        for (int i = 0; i < 2; i++) {
            xA[i] = pk2(p[i][0], p[i][1]);
            xB[i] = pk2(p[i][2], p[i][3]);
        }

        if (s + 1 < T) {
            int tn = dir ? (T - 2 - s) : (s + 1);
            #pragma unroll
            for (int i = 0; i < 2; i++) {
                #pragma unroll
                for (int g = 0; g < 4; g++)
                    p[i][g] = __ldg(xgp[i] + (size_t)tn * 512 + g * 64);
            }
        }

        ULL A0[8], A1[8];
        #pragma unroll
        for (int r = 0; r < 8; r++) {
            bool own = (r >> 1) == kh;
            A0[r] = own ? biasA : 0ULL;
            A1[r] = own ? biasB : 0ULL;
        }

        #pragma unroll
        for (int kk2 = 0; kk2 < 16; kk2++) {
            int kk = kb + kk2;
            ulonglong2 w2  = *(const ulonglong2*)(wt + kk * 256 + jj * 4);
            ulonglong2 hv0 = *(const ulonglong2*)(h_s + kk * AS2);
            ulonglong2 hv1 = *(const ulonglong2*)(h_s + kk * AS2 + 2);
            ulonglong2 hv2 = *(const ulonglong2*)(h_s + kk * AS2 + 4);
            ulonglong2 hv3 = *(const ulonglong2*)(h_s + kk * AS2 + 6);
            fma2(A0[0], w2.x, hv0.x);  fma2(A1[0], w2.y, hv0.x);
            fma2(A0[1], w2.x, hv0.y);  fma2(A1[1], w2.y, hv0.y);
            fma2(A0[2], w2.x, hv1.x);  fma2(A1[2], w2.y, hv1.x);
            fma2(A0[3], w2.x, hv1.y);  fma2(A1[3], w2.y, hv1.y);
            fma2(A0[4], w2.x, hv2.x);  fma2(A1[4], w2.y, hv2.x);
            fma2(A0[5], w2.x, hv2.y);  fma2(A1[5], w2.y, hv2.y);
            fma2(A0[6], w2.x, hv3.x);  fma2(A1[6], w2.y, hv3.x);
            fma2(A0[7], w2.x, hv3.y);  fma2(A1[7], w2.y, hv3.y);
        }
        __syncthreads();

        #pragma unroll
        for (int r = 0; r < 8; r++) {
            int kr = r >> 1, i = r & 1;
            int m = kh ^ kr;
            if (m != 0)
                red[((kr * 3 + (m - 1)) * 2 + i) * 64 + jj]
                    = make_ulonglong2(A0[r], A1[r]);
        }
        __syncthreads();

        ULL B0[2], B1[2];
        #pragma unroll
        for (int r = 0; r < 8; r++) {
            if ((r >> 1) == kh) { B0[r & 1] = A0[r]; B1[r & 1] = A1[r]; }
        }
        #pragma unroll
        for (int m = 1; m <= 3; m++) {
            #pragma unroll
            for (int i = 0; i < 2; i++) {
                ulonglong2 q = red[((kh * 3 + (m - 1)) * 2 + i) * 64 + jj];
                add2(B0[i], q.x);
                add2(B1[i], q.y);
            }
        }

        #pragma unroll
        for (int i = 0; i < 2; i++) {
            add2(B0[i], xA[i]);
            add2(B1[i], xB[i]);
            float ai, af, ag, ao;
            unpk(B0[i], ai, af);
            unpk(B1[i], ag, ao);
            cs[i] = sig_f(af) * cs[i] + sig_f(ai) * tanh_f(ag);
            hh[i] = sig_f(ao) * tanh_f(cs[i]);
        }

        *(ulonglong2*)(h_s + jj * AS2 + 2 * kh)
            = make_ulonglong2(dup2(hh[0]), dup2(hh[1]));
        __syncthreads();
    }

    #pragma unroll
    for (int i = 0; i < 2; i++) {
        int row = 2 * kh + i;
        g_hcat[(size_t)(b0 + row) * 128 + dof + jj] = hh[i];
    }
}

// ---------------------------------------------------------------------------
// Kernel 4: FC head (proven R15).
// ---------------------------------------------------------------------------
__global__ void __launch_bounds__(256) head_kernel(
    const float* __restrict__ fc1W, const float* __restrict__ fc1b,
    const float* __restrict__ fc2W, const float* __restrict__ fc2b,
    float* __restrict__ out)
{
    __shared__ float f1[4][64];
    const int j = threadIdx.x;
    const int r = j >> 6;
    const int o = j & 63;
    const int b = blockIdx.x * 4 + r;

    const float* h = g_hcat + (size_t)b * 128;
    const float* w = fc1W + o * 128;
    float a0 = 0.f, a1 = 0.f, a2 = 0.f, a3 = 0.f;
    #pragma unroll
    for (int kk = 0; kk < 128; kk += 4) {
        float4 wv = *(const float4*)(w + kk);
        float4 hv = *(const float4*)(h + kk);
        a0 = fmaf(wv.x, hv.x, a0);
        a1 = fmaf(wv.y, hv.y, a1);
        a2 = fmaf(wv.z, hv.z, a2);
        a3 = fmaf(wv.w, hv.w, a3);
    }
    f1[r][o] = fmaxf(fc1b[o] + (a0 + a1) + (a2 + a3), 0.0f);
    __syncthreads();

    if (o < 2) {
        const float* w2 = fc2W + o * 64;
        float c0 = 0.f, c1 = 0.f;
        #pragma unroll
        for (int kk = 0; kk < 64; kk += 2) {
            c0 = fmaf(w2[kk],     f1[r][kk],     c0);
            c1 = fmaf(w2[kk + 1], f1[r][kk + 1], c1);
        }
        out[(size_t)b * 2 + o] = fc2b[o] + c0 + c1;
    }
}

// ---------------------------------------------------------------------------
// Launcher
// ---------------------------------------------------------------------------
extern "C" void kernel_launch(void* const* d_in, const int* in_sizes, int n_in,
                              void* d_out, int out_size)
{
    const float* x      = (const float*)d_in[0];
    const float* Wih0f  = (const float*)d_in[1];
    const float* Whh0f  = (const float*)d_in[2];
    const float* bih0f  = (const float*)d_in[3];
    const float* bhh0f  = (const float*)d_in[4];
    const float* Wih0b  = (const float*)d_in[5];
    const float* Whh0b  = (const float*)d_in[6];
    const float* bih0b  = (const float*)d_in[7];
    const float* bhh0b  = (const float*)d_in[8];
    const float* Wih1f  = (const float*)d_in[9];
    const float* Whh1f  = (const float*)d_in[10];
    const float* bih1f  = (const float*)d_in[11];
    const float* bhh1f  = (const float*)d_in[12];
    const float* Wih1b  = (const float*)d_in[13];
    const float* Whh1b  = (const float*)d_in[14];
    const float* bih1b  = (const float*)d_in[15];
    const float* bhh1b  = (const float*)d_in[16];
    const float* fc1W   = (const float*)d_in[17];
    const float* fc1b   = (const float*)d_in[18];
    const float* fc2W   = (const float*)d_in[19];
    const float* fc2b   = (const float*)d_in[20];
    float* out = (float*)d_out;

    cudaFuncSetAttribute(lstm0_kernel,
                         cudaFuncAttributeMaxDynamicSharedMemorySize, SMEML);
    cudaFuncSetAttribute(xg_gemm_kernel,
                         cudaFuncAttributeMaxDynamicSharedMemorySize, SMEMG);
    cudaFuncSetAttribute(lstm1_kernel,
                         cudaFuncAttributeMaxDynamicSharedMemorySize, SMEML);

    wprep_kernel<<<256, 256>>>(Wih1f, Wih1b);

    dim3 grid(B / 8, 2);
    lstm0_kernel<<<grid, 256, SMEML>>>(x,
                                       Wih0f, Whh0f, bih0f, bhh0f,
                                       Wih0b, Whh0b, bih0b, bhh0b);

    xg_gemm_kernel<<<B * T / 128, 256, SMEMG>>>();

    lstm1_kernel<<<grid, 256, SMEML>>>(Whh1f, bih1f, bhh1f,
                                       Whh1b, bih1b, bhh1b);

    head_kernel<<<B / 4, 256>>>(fc1W, fc1b, fc2W, fc2b, out);
}